// round 2
// baseline (speedup 1.0000x reference)
#include <cuda_runtime.h>
#include <cstdint>

#define BB 4
#define TT 4096
#define CC 1024
#define HH 64
constexpr int MROWS = BB * TT;  // 16384

// Scratch for projected q,k,v (device globals: no allocation allowed)
__device__ float g_q[MROWS * HH];
__device__ float g_k[MROWS * HH];
__device__ float g_v[MROWS * HH];

// ---------------- f32x2 packed-FMA helpers (Blackwell-only) ----------------
using u64 = unsigned long long;

__device__ __forceinline__ u64 pk2(float lo, float hi) {
    u64 r;
    asm("mov.b64 %0, {%1, %2};" : "=l"(r) : "f"(lo), "f"(hi));
    return r;
}
__device__ __forceinline__ void fma2(u64& d, u64 a, u64 b) {
    asm("fma.rn.f32x2 %0, %1, %2, %0;" : "+l"(d) : "l"(a), "l"(b));
}
__device__ __forceinline__ void mul2(u64& d, u64 a) {
    asm("mul.rn.f32x2 %0, %0, %1;" : "+l"(d) : "l"(a));
}
__device__ __forceinline__ float2 upk(u64 v) {
    float2 f;
    asm("mov.b64 {%0, %1}, %2;" : "=f"(f.x), "=f"(f.y) : "l"(v));
    return f;
}

// ---------------------------------------------------------------------------
// Kernel 1: fused QKV projection.  qkv[m, 0:192] = x[m, :] @ [Wq|Wk|Wv]
// GEMM M=16384, N=192, K=1024.  Block: 64 rows x 192 cols, 256 threads,
// thread tile 4 rows x 12 cols (6 f32x2 pairs).
// ---------------------------------------------------------------------------
__global__ __launch_bounds__(256) void proj_kernel(
    const float* __restrict__ x,
    const float* __restrict__ Wq,
    const float* __restrict__ Wk,
    const float* __restrict__ Wv)
{
    __shared__ float Xs[64][36];     // 64 rows x 32 k (pad to 36)
    __shared__ float Ws[32][196];    // 32 k x 192 n (pad to 196)

    const int tid = threadIdx.x;
    const int row0 = blockIdx.x * 64;
    const int rg = tid >> 4;   // 0..15  (rows rg*4 .. rg*4+3)
    const int cg = tid & 15;   // 0..15  (cols cg*12 .. cg*12+11)

    u64 acc[4][6];
#pragma unroll
    for (int i = 0; i < 4; i++)
#pragma unroll
        for (int j = 0; j < 6; j++) acc[i][j] = 0ull;

    for (int k0 = 0; k0 < CC; k0 += 32) {
        // load X chunk: 64 x 32 floats = 512 float4
#pragma unroll
        for (int e = 0; e < 2; e++) {
            int fid = tid + e * 256;
            int r = fid >> 3, kf = fid & 7;
            *(float4*)&Xs[r][kf * 4] =
                *(const float4*)&x[(size_t)(row0 + r) * CC + k0 + kf * 4];
        }
        // load W chunk: 32 x 192 floats = 1536 float4
#pragma unroll
        for (int e = 0; e < 6; e++) {
            int fid = tid + e * 256;
            int kk = fid / 48, nf = fid % 48;
            int n = nf * 4;
            int kg = k0 + kk;
            const float* src;
            if (n < 64)        src = &Wq[kg * 64 + n];
            else if (n < 128)  src = &Wk[kg * 64 + (n - 64)];
            else               src = &Wv[kg * 64 + (n - 128)];
            *(float4*)&Ws[kk][n] = *(const float4*)src;
        }
        __syncthreads();

#pragma unroll 8
        for (int kk = 0; kk < 32; kk++) {
            float xv[4];
#pragma unroll
            for (int i = 0; i < 4; i++) xv[i] = Xs[rg * 4 + i][kk];
            ulonglong2 w2[3];
            const ulonglong2* wrow = (const ulonglong2*)&Ws[kk][cg * 12];
#pragma unroll
            for (int j = 0; j < 3; j++) w2[j] = wrow[j];
#pragma unroll
            for (int i = 0; i < 4; i++) {
                u64 xp = pk2(xv[i], xv[i]);
                fma2(acc[i][0], xp, w2[0].x);
                fma2(acc[i][1], xp, w2[0].y);
                fma2(acc[i][2], xp, w2[1].x);
                fma2(acc[i][3], xp, w2[1].y);
                fma2(acc[i][4], xp, w2[2].x);
                fma2(acc[i][5], xp, w2[2].y);
            }
        }
        __syncthreads();
    }

    // store: route n<64 -> q, n<128 -> k, else v
#pragma unroll
    for (int i = 0; i < 4; i++) {
        int m = row0 + rg * 4 + i;
#pragma unroll
        for (int jj = 0; jj < 6; jj++) {
            float2 v = upk(acc[i][jj]);
            int n0 = cg * 12 + jj * 2;
#pragma unroll
            for (int e = 0; e < 2; e++) {
                int n = n0 + e;
                float val = (e == 0) ? v.x : v.y;
                if (n < 64)        g_q[(size_t)m * 64 + n] = val;
                else if (n < 128)  g_k[(size_t)m * 64 + (n - 64)] = val;
                else               g_v[(size_t)m * 64 + (n - 128)] = val;
            }
        }
    }
}

// ---------------------------------------------------------------------------
// Kernel 2: flash attention, causal.  BQ = BK = 64, head dim 64.
// 256 threads.  Online softmax; O accumulators in registers (f32x2 pairs).
// P is stored DUPLICATED (p,p) in smem so the PV phase can use f32x2 with a
// single LDS.64 broadcast operand (no pack MOVs in the hot loop).
// ---------------------------------------------------------------------------
#define LDSK 68   // row stride (floats) for Q/K/V tiles (64 + 4 pad)
#define LDSP 136  // row stride (floats) for duplicated P tile (128 + 8 pad)

__global__ __launch_bounds__(256) void attn_kernel(float* __restrict__ out)
{
    extern __shared__ float sm[];
    float* Qs  = sm;                  // 64*68
    float* Ks  = Qs + 64 * LDSK;      // 64*68
    float* Vs  = Ks + 64 * LDSK;      // 64*68
    float* Pd  = Vs + 64 * LDSK;      // 64*136 (duplicated P)
    float* mrow = Pd + 64 * LDSP;     // 64
    float* lrow = mrow + 64;          // 64
    float* arow = lrow + 64;          // 64

    const int tid = threadIdx.x;
    const int b   = blockIdx.y;
    const int qi  = (gridDim.x - 1) - blockIdx.x;  // longest blocks first
    const float scale = 0.03125f;  // 1024^-0.5 (reference scales by n_embd^-0.5)

    const int rg = tid >> 4;   // 0..15 : S/O rows  rg + 16*i
    const int cg = tid & 15;   // 0..15 : S cols cg + 16*j ; O cols cg*4..cg*4+3

    // load Q tile (scaled)
    const size_t qbase = ((size_t)b * TT + (size_t)qi * 64) * HH;
#pragma unroll
    for (int e = 0; e < 4; e++) {
        int fid = tid + e * 256;
        int r = fid >> 4, hf = fid & 15;
        float4 v = *(const float4*)&g_q[qbase + (size_t)r * 64 + hf * 4];
        v.x *= scale; v.y *= scale; v.z *= scale; v.w *= scale;
        *(float4*)&Qs[r * LDSK + hf * 4] = v;
    }
    if (tid < 64) { mrow[tid] = -1e30f; lrow[tid] = 0.f; }

    u64 o[4][2];
#pragma unroll
    for (int i = 0; i < 4; i++) { o[i][0] = 0ull; o[i][1] = 0ull; }

    const int srow = tid >> 2;   // softmax row (0..63)
    const int part = tid & 3;    // softmax quarter

    for (int kt = 0; kt <= qi; kt++) {
        __syncthreads();  // prev tile's phase-C reads done; Q load done (kt=0)

        const size_t kbase = ((size_t)b * TT + (size_t)kt * 64) * HH;
#pragma unroll
        for (int e = 0; e < 4; e++) {
            int fid = tid + e * 256;
            int r = fid >> 4, hf = fid & 15;
            *(float4*)&Ks[r * LDSK + hf * 4] =
                *(const float4*)&g_k[kbase + (size_t)r * 64 + hf * 4];
            *(float4*)&Vs[r * LDSK + hf * 4] =
                *(const float4*)&g_v[kbase + (size_t)r * 64 + hf * 4];
        }
        __syncthreads();

        // ---- Phase A: S = Q K^T (register tile 4x4, f32x2 over head dim) ----
        u64 s2[4][4];
#pragma unroll
        for (int i = 0; i < 4; i++)
#pragma unroll
            for (int j = 0; j < 4; j++) s2[i][j] = 0ull;

#pragma unroll 4
        for (int hg = 0; hg < 16; hg++) {
            ulonglong2 q2[4], k2[4];
#pragma unroll
            for (int i = 0; i < 4; i++)
                q2[i] = *(const ulonglong2*)&Qs[(rg + 16 * i) * LDSK + hg * 4];
#pragma unroll
            for (int j = 0; j < 4; j++)
                k2[j] = *(const ulonglong2*)&Ks[(cg + 16 * j) * LDSK + hg * 4];
#pragma unroll
            for (int i = 0; i < 4; i++)
#pragma unroll
                for (int j = 0; j < 4; j++) {
                    fma2(s2[i][j], q2[i].x, k2[j].x);
                    fma2(s2[i][j], q2[i].y, k2[j].y);
                }
        }
        const bool diag = (kt == qi);
#pragma unroll
        for (int i = 0; i < 4; i++) {
            int r_ = rg + 16 * i;
#pragma unroll
            for (int j = 0; j < 4; j++) {
                int c_ = cg + 16 * j;
                float2 p = upk(s2[i][j]);
                float s = p.x + p.y;
                if (diag && c_ > r_) s = -1e30f;
                Pd[r_ * LDSP + 2 * c_] = s;
            }
        }
        __syncthreads();

        // ---- Phase B: online softmax (4 threads per row) ----
        {
            float vals[16];
#pragma unroll
            for (int e = 0; e < 16; e++)
                vals[e] = Pd[srow * LDSP + 2 * (part * 16 + e)];
            float mt = vals[0];
#pragma unroll
            for (int e = 1; e < 16; e++) mt = fmaxf(mt, vals[e]);
            mt = fmaxf(mt, __shfl_xor_sync(0xffffffffu, mt, 1));
            mt = fmaxf(mt, __shfl_xor_sync(0xffffffffu, mt, 2));
            float mold = mrow[srow];
            float mnew = fmaxf(mold, mt);
            float sum = 0.f;
#pragma unroll
            for (int e = 0; e < 16; e++) {
                float p = __expf(vals[e] - mnew);
                sum += p;
                *(u64*)&Pd[srow * LDSP + 2 * (part * 16 + e)] = pk2(p, p);
            }
            sum += __shfl_xor_sync(0xffffffffu, sum, 1);
            sum += __shfl_xor_sync(0xffffffffu, sum, 2);
            if (part == 0) {
                float alpha = __expf(mold - mnew);
                lrow[srow] = lrow[srow] * alpha + sum;
                mrow[srow] = mnew;
                arow[srow] = alpha;
            }
        }
        __syncthreads();

        // ---- Phase C: O = O*alpha + P V (f32x2 over output cols) ----
#pragma unroll
        for (int i = 0; i < 4; i++) {
            float a = arow[rg + 16 * i];
            u64 ap = pk2(a, a);
            mul2(o[i][0], ap);
            mul2(o[i][1], ap);
        }
#pragma unroll 4
        for (int sg = 0; sg < 16; sg++) {
            ulonglong2 v2[4];
#pragma unroll
            for (int ss = 0; ss < 4; ss++)
                v2[ss] = *(const ulonglong2*)&Vs[(sg * 4 + ss) * LDSK + cg * 4];
#pragma unroll
            for (int i = 0; i < 4; i++) {
                const float* prow = &Pd[(rg + 16 * i) * LDSP];
#pragma unroll
                for (int ss = 0; ss < 4; ss++) {
                    u64 p = *(const u64*)&prow[2 * (sg * 4 + ss)];
                    fma2(o[i][0], p, v2[ss].x);
                    fma2(o[i][1], p, v2[ss].y);
                }
            }
        }
    }

    // ---- epilogue: divide by l, store ----
#pragma unroll
    for (int i = 0; i < 4; i++) {
        int r_ = rg + 16 * i;
        float inv = 1.f / lrow[r_];
        float2 a = upk(o[i][0]);
        float2 c = upk(o[i][1]);
        float4 res;
        res.x = a.x * inv; res.y = a.y * inv;
        res.z = c.x * inv; res.w = c.y * inv;
        *(float4*)&out[(((size_t)b * TT + (size_t)qi * 64 + r_) * HH) + cg * 4] = res;
    }
}

// ---------------------------------------------------------------------------
extern "C" void kernel_launch(void* const* d_in, const int* in_sizes, int n_in,
                              void* d_out, int out_size)
{
    const float* x  = (const float*)d_in[0];
    const float* Wq = (const float*)d_in[1];
    const float* Wk = (const float*)d_in[2];
    const float* Wv = (const float*)d_in[3];
    float* out = (float*)d_out;

    const int attn_smem = (3 * 64 * LDSK + 64 * LDSP + 192) * (int)sizeof(float); // 87808
    cudaFuncSetAttribute(attn_kernel,
                         cudaFuncAttributeMaxDynamicSharedMemorySize, attn_smem);

    proj_kernel<<<MROWS / 64, 256>>>(x, Wq, Wk, Wv);
    attn_kernel<<<dim3(TT / 64, BB), 256, attn_smem>>>(out);
}

// round 5
// speedup vs baseline: 3.6838x; 3.6838x over previous
#include <cuda_runtime.h>
#include <cuda_bf16.h>
#include <cstdint>

#define BB 4
#define TT 4096
#define CC 1024
#define HH 64
constexpr int MROWS = BB * TT;  // 16384

// ---------------- device scratch (q scaled by 1/32; all [m][h] bf16) -------
__device__ __nv_bfloat16 g_wth[192 * CC], g_wtl[192 * CC];   // W^T hi/lo [n][c]
__device__ __nv_bfloat16 g_qh[MROWS * HH], g_ql[MROWS * HH];
__device__ __nv_bfloat16 g_kh[MROWS * HH], g_kl[MROWS * HH];
__device__ __nv_bfloat16 g_vh[MROWS * HH], g_vl[MROWS * HH];

// ---------------- helpers ----------------
__device__ __forceinline__ uint32_t smem_u32(const void* p) {
    uint32_t a;
    asm("{ .reg .u64 t; cvta.to.shared.u64 t, %1; cvt.u32.u64 %0, t; }" : "=r"(a) : "l"(p));
    return a;
}
__device__ __forceinline__ uint32_t pkbf(float lo, float hi) {  // bf16x2 {lo,hi}
    uint32_t d;
    asm("cvt.rn.bf16x2.f32 %0, %1, %2;" : "=r"(d) : "f"(hi), "f"(lo));
    return d;
}
__device__ __forceinline__ float bfr(float x) { return __bfloat162float(__float2bfloat16_rn(x)); }
__device__ __forceinline__ float ex2f(float x) {
    float r; asm("ex2.approx.ftz.f32 %0, %1;" : "=f"(r) : "f"(x)); return r;
}
__device__ __forceinline__ void ldsm4(uint4& d, uint32_t a) {
    asm volatile("ldmatrix.sync.aligned.m8n8.x4.shared.b16 {%0,%1,%2,%3}, [%4];"
                 : "=r"(d.x), "=r"(d.y), "=r"(d.z), "=r"(d.w) : "r"(a));
}
__device__ __forceinline__ void ldsm4t(uint4& d, uint32_t a) {
    asm volatile("ldmatrix.sync.aligned.m8n8.x4.trans.shared.b16 {%0,%1,%2,%3}, [%4];"
                 : "=r"(d.x), "=r"(d.y), "=r"(d.z), "=r"(d.w) : "r"(a));
}
__device__ __forceinline__ void mmabf(float* c, const uint4& a, uint32_t b0, uint32_t b1) {
    asm volatile("mma.sync.aligned.m16n8k16.row.col.f32.bf16.bf16.f32 "
                 "{%0,%1,%2,%3}, {%4,%5,%6,%7}, {%8,%9}, {%0,%1,%2,%3};"
                 : "+f"(c[0]), "+f"(c[1]), "+f"(c[2]), "+f"(c[3])
                 : "r"(a.x), "r"(a.y), "r"(a.z), "r"(a.w), "r"(b0), "r"(b1));
}
__device__ __forceinline__ void mmabf_a(float* c, uint32_t a0, uint32_t a1, uint32_t a2,
                                        uint32_t a3, uint32_t b0, uint32_t b1) {
    asm volatile("mma.sync.aligned.m16n8k16.row.col.f32.bf16.bf16.f32 "
                 "{%0,%1,%2,%3}, {%4,%5,%6,%7}, {%8,%9}, {%0,%1,%2,%3};"
                 : "+f"(c[0]), "+f"(c[1]), "+f"(c[2]), "+f"(c[3])
                 : "r"(a0), "r"(a1), "r"(a2), "r"(a3), "r"(b0), "r"(b1));
}
#define CPA(dst, src)  asm volatile("cp.async.cg.shared.global [%0], [%1], 16;" :: "r"(dst), "l"(src))
#define CPCOMMIT()     asm volatile("cp.async.commit_group;" ::: "memory")
#define CPWAIT0()      asm volatile("cp.async.wait_group 0;" ::: "memory")

// ---------------------------------------------------------------------------
// Kernel 0: W^T hi/lo split.  g_wt*[n][c] = W*(c, n%64)
// ---------------------------------------------------------------------------
__global__ void prep_kernel(const float* __restrict__ Wq, const float* __restrict__ Wk,
                            const float* __restrict__ Wv) {
    int n = blockIdx.x;  // 0..191
    const float* W = (n < 64) ? Wq : ((n < 128) ? Wk : Wv);
    int col = n & 63;
    for (int c = threadIdx.x; c < CC; c += blockDim.x) {
        float w = W[c * 64 + col];
        g_wth[n * CC + c] = __float2bfloat16_rn(w);
        g_wtl[n * CC + c] = __float2bfloat16_rn(w - bfr(w));
    }
}

// ---------------------------------------------------------------------------
// Kernel 1: QKV projection, mma.sync bf16 3-term.
// Block tile 128(M) x 192(N), K chunks of 64. 8 warps = 4(M) x 2(N).
// smem: A stages 2 x (hi 128*144 + lo) = 73728; B stages 2 x (hi 192*144 + lo)
// ---------------------------------------------------------------------------
#define PRJ_ASTG 36864
#define PRJ_BOFF 73728
#define PRJ_BSTG 55296
#define PRJ_SMEM (PRJ_BOFF + 2 * PRJ_BSTG)   // 184320

__global__ __launch_bounds__(256) void proj_kernel(const float* __restrict__ x) {
    extern __shared__ char sm[];
    uint32_t sb = smem_u32(sm);
    const int tid = threadIdx.x;
    const int lane = tid & 31, wid = tid >> 5;
    const int wm = wid & 3, wn = wid >> 2;
    const int row0 = blockIdx.x * 128;
    const int arow = tid >> 1, acs = (tid & 1) * 32;

    float c[2][12][4];
#pragma unroll
    for (int i = 0; i < 2; i++)
#pragma unroll
        for (int t = 0; t < 12; t++)
#pragma unroll
            for (int e = 0; e < 4; e++) c[i][t][e] = 0.f;

    float4 xr[8];
    // prefetch x chunk 0 into regs
    {
        const float4* s = (const float4*)(x + (size_t)(row0 + arow) * CC + acs);
#pragma unroll
        for (int g = 0; g < 8; g++) xr[g] = s[g];
    }
    // prefetch B chunk 0 into stage 0
    {
        uint32_t Bb = sb + PRJ_BOFF;
#pragma unroll
        for (int e = 0; e < 12; e++) {
            int idx = tid + (e % 6) * 256;
            int row = idx >> 3, j = idx & 7;
            const char* src = (e < 6 ? (const char*)g_wth : (const char*)g_wtl)
                              + (size_t)row * 2048 + j * 16;
            CPA(Bb + (e < 6 ? 0u : (uint32_t)PRJ_BSTG / 2) + row * 144 + j * 16, src);
        }
        CPCOMMIT();
    }

    for (int kc = 0; kc < 16; kc++) {
        const uint32_t Ab = sb + (kc & 1) * PRJ_ASTG;
        const uint32_t Bb = sb + PRJ_BOFF + (kc & 1) * PRJ_BSTG;
        // convert + store A (this chunk) from regs
        {
            char* dst = sm + (kc & 1) * PRJ_ASTG + arow * 144 + acs * 2;
#pragma unroll
            for (int g = 0; g < 4; g++) {
                float e[8] = {xr[2 * g].x, xr[2 * g].y, xr[2 * g].z, xr[2 * g].w,
                              xr[2 * g + 1].x, xr[2 * g + 1].y, xr[2 * g + 1].z, xr[2 * g + 1].w};
                uint4 H, L;
                uint32_t* hp = (uint32_t*)&H;
                uint32_t* lp = (uint32_t*)&L;
#pragma unroll
                for (int q = 0; q < 4; q++) {
                    float a0 = e[2 * q], a1 = e[2 * q + 1];
                    hp[q] = pkbf(a0, a1);
                    lp[q] = pkbf(a0 - bfr(a0), a1 - bfr(a1));
                }
                *(uint4*)(dst + g * 16) = H;
                *(uint4*)(dst + 18432 + g * 16) = L;
            }
        }
        // prefetch next x chunk into regs
        if (kc < 15) {
            const float4* s = (const float4*)(x + (size_t)(row0 + arow) * CC + (kc + 1) * 64 + acs);
#pragma unroll
            for (int g = 0; g < 8; g++) xr[g] = s[g];
        }
        CPWAIT0();
        __syncthreads();
        // issue B prefetch for next chunk
        if (kc < 15) {
            uint32_t Bn = sb + PRJ_BOFF + ((kc + 1) & 1) * PRJ_BSTG;
            int k0 = (kc + 1) * 64;
#pragma unroll
            for (int e = 0; e < 12; e++) {
                int idx = tid + (e % 6) * 256;
                int row = idx >> 3, j = idx & 7;
                const char* src = (e < 6 ? (const char*)g_wth : (const char*)g_wtl)
                                  + (size_t)row * 2048 + k0 * 2 + j * 16;
                CPA(Bn + (e < 6 ? 0u : (uint32_t)PRJ_BSTG / 2) + row * 144 + j * 16, src);
            }
            CPCOMMIT();
        }
        // mma over 4 k16 steps
#pragma unroll
        for (int ks = 0; ks < 4; ks++) {
            uint4 ah[2], al[2];
#pragma unroll
            for (int i = 0; i < 2; i++) {
                uint32_t r = wm * 32 + i * 16 + (lane & 15);
                uint32_t cb = ks * 32 + (lane >> 4) * 16;
                ldsm4(ah[i], Ab + r * 144 + cb);
                ldsm4(al[i], Ab + 18432 + r * 144 + cb);
            }
#pragma unroll
            for (int np = 0; np < 6; np++) {
                uint32_t rn = wn * 96 + np * 16 + (lane & 7) + ((lane >> 4) << 3);
                uint32_t cb = ks * 32 + ((lane >> 3) & 1) * 16;
                uint4 bh, bl;
                ldsm4(bh, Bb + rn * 144 + cb);
                ldsm4(bl, Bb + PRJ_BSTG / 2 + rn * 144 + cb);
#pragma unroll
                for (int i = 0; i < 2; i++) {
                    mmabf(c[i][np * 2], ah[i], bh.x, bh.y);
                    mmabf(c[i][np * 2 + 1], ah[i], bh.z, bh.w);
                    mmabf(c[i][np * 2], al[i], bh.x, bh.y);
                    mmabf(c[i][np * 2 + 1], al[i], bh.z, bh.w);
                    mmabf(c[i][np * 2], ah[i], bl.x, bl.y);
                    mmabf(c[i][np * 2 + 1], ah[i], bl.z, bl.w);
                }
            }
        }
    }
    // epilogue: hi/lo split, route q/k/v
#pragma unroll
    for (int i = 0; i < 2; i++) {
#pragma unroll
        for (int nt = 0; nt < 12; nt++) {
            int n = wn * 96 + nt * 8 + (lane & 3) * 2;
            int tgt = n >> 6, nn = n & 63;
            float sc = (tgt == 0) ? 0.03125f : 1.0f;
            uint32_t* dh = (uint32_t*)((tgt == 0) ? g_qh : (tgt == 1) ? g_kh : g_vh);
            uint32_t* dl = (uint32_t*)((tgt == 0) ? g_ql : (tgt == 1) ? g_kl : g_vl);
#pragma unroll
            for (int h = 0; h < 2; h++) {
                int m = row0 + wm * 32 + i * 16 + (lane >> 2) + h * 8;
                float a0 = c[i][nt][2 * h] * sc, a1 = c[i][nt][2 * h + 1] * sc;
                dh[(size_t)m * 32 + nn / 2] = pkbf(a0, a1);
                dl[(size_t)m * 32 + nn / 2] = pkbf(a0 - bfr(a0), a1 - bfr(a1));
            }
        }
    }
}

// ---------------------------------------------------------------------------
// Kernel 2: flash attention, mma.sync bf16 3-term.  BQ=BK=64, 4 warps.
// smem: 2 stages x (Kh 9216 | Kl | Vh | Vl) = 73728.
// ---------------------------------------------------------------------------
#define ATN_STG 36864
#define ATN_SMEM (2 * ATN_STG)

__global__ __launch_bounds__(128) void attn_kernel(float* __restrict__ out) {
    extern __shared__ char sm[];
    uint32_t sb = smem_u32(sm);
    const int tid = threadIdx.x;
    const int lane = tid & 31, wid = tid >> 5;
    const int qq = 63 - (blockIdx.x >> 2);   // longest blocks first
    const int b = blockIdx.x & 3;
    const int nk = qq + 1;
    const float L2E = 1.4426950408889634f;

    // stage Q (64x64 hi/lo) into stage-0 K slots via cp.async
    {
#pragma unroll
        for (int e = 0; e < 8; e++) {
            int rem = tid + (e & 3) * 128;
            int row = rem >> 3, j = rem & 7;
            const char* src = (e < 4 ? (const char*)g_qh : (const char*)g_ql)
                              + ((size_t)(b * TT + qq * 64 + row)) * 128 + j * 16;
            CPA(sb + (e < 4 ? 0 : 9216) + row * 144 + j * 16, src);
        }
        CPCOMMIT();
        CPWAIT0();
        __syncthreads();
    }
    // Q frags into regs (A operand, m16k16 x4 ktiles, hi/lo)
    uint4 qh[4], ql[4];
#pragma unroll
    for (int ks = 0; ks < 4; ks++) {
        uint32_t r = wid * 16 + (lane & 15);
        uint32_t cb = ks * 32 + (lane >> 4) * 16;
        ldsm4(qh[ks], sb + r * 144 + cb);
        ldsm4(ql[ks], sb + 9216 + r * 144 + cb);
    }
    __syncthreads();

    // prefetch K/V tile 0 into stage 0
#pragma unroll
    for (int e = 0; e < 16; e++) {
        int arr = e >> 2;
        int rem = tid + (e & 3) * 128;
        int row = rem >> 3, j = rem & 7;
        const char* src = (arr == 0 ? (const char*)g_kh : arr == 1 ? (const char*)g_kl
                           : arr == 2 ? (const char*)g_vh : (const char*)g_vl)
                          + ((size_t)(b * TT + row)) * 128 + j * 16;
        CPA(sb + arr * 9216 + row * 144 + j * 16, src);
    }
    CPCOMMIT();

    float o[8][4];
#pragma unroll
    for (int t = 0; t < 8; t++)
#pragma unroll
        for (int e = 0; e < 4; e++) o[t][e] = 0.f;
    float m0 = -1e30f, m1 = -1e30f, l0 = 0.f, l1 = 0.f;

    const int gr0 = qq * 64 + wid * 16 + (lane >> 2);

    for (int kt = 0; kt < nk; kt++) {
        CPWAIT0();
        __syncthreads();
        const uint32_t Kb = sb + (kt & 1) * ATN_STG;
        // issue prefetch kt+1
        if (kt + 1 < nk) {
            uint32_t Nb = sb + ((kt + 1) & 1) * ATN_STG;
#pragma unroll
            for (int e = 0; e < 16; e++) {
                int arr = e >> 2;
                int rem = tid + (e & 3) * 128;
                int row = rem >> 3, j = rem & 7;
                const char* src = (arr == 0 ? (const char*)g_kh : arr == 1 ? (const char*)g_kl
                                   : arr == 2 ? (const char*)g_vh : (const char*)g_vl)
                                  + ((size_t)(b * TT + (kt + 1) * 64 + row)) * 128 + j * 16;
                CPA(Nb + arr * 9216 + row * 144 + j * 16, src);
            }
            CPCOMMIT();
        }

        // ---- S = Q K^T ----
        float sc[8][4];
#pragma unroll
        for (int t = 0; t < 8; t++)
#pragma unroll
            for (int e = 0; e < 4; e++) sc[t][e] = 0.f;
#pragma unroll
        for (int ks = 0; ks < 4; ks++) {
#pragma unroll
            for (int np = 0; np < 4; np++) {
                uint32_t rn = np * 16 + (lane & 7) + ((lane >> 4) << 3);
                uint32_t cb = ks * 32 + ((lane >> 3) & 1) * 16;
                uint4 bh, bl;
                ldsm4(bh, Kb + rn * 144 + cb);
                ldsm4(bl, Kb + 9216 + rn * 144 + cb);
                mmabf(sc[np * 2], qh[ks], bh.x, bh.y);
                mmabf(sc[np * 2 + 1], qh[ks], bh.z, bh.w);
                mmabf(sc[np * 2], ql[ks], bh.x, bh.y);
                mmabf(sc[np * 2 + 1], ql[ks], bh.z, bh.w);
                mmabf(sc[np * 2], qh[ks], bl.x, bl.y);
                mmabf(sc[np * 2 + 1], qh[ks], bl.z, bl.w);
            }
        }
        // ---- mask (diag tile only) ----
        if (kt == qq) {
#pragma unroll
            for (int nt = 0; nt < 8; nt++) {
                int gc = kt * 64 + nt * 8 + (lane & 3) * 2;
                if (gc > gr0) sc[nt][0] = -1e30f;
                if (gc + 1 > gr0) sc[nt][1] = -1e30f;
                if (gc > gr0 + 8) sc[nt][2] = -1e30f;
                if (gc + 1 > gr0 + 8) sc[nt][3] = -1e30f;
            }
        }
        // ---- online softmax (rows r0, r0+8 per thread; quad reduce) ----
        float mt0 = -1e30f, mt1 = -1e30f;
#pragma unroll
        for (int nt = 0; nt < 8; nt++) {
            mt0 = fmaxf(mt0, fmaxf(sc[nt][0], sc[nt][1]));
            mt1 = fmaxf(mt1, fmaxf(sc[nt][2], sc[nt][3]));
        }
        mt0 = fmaxf(mt0, __shfl_xor_sync(0xffffffffu, mt0, 1));
        mt0 = fmaxf(mt0, __shfl_xor_sync(0xffffffffu, mt0, 2));
        mt1 = fmaxf(mt1, __shfl_xor_sync(0xffffffffu, mt1, 1));
        mt1 = fmaxf(mt1, __shfl_xor_sync(0xffffffffu, mt1, 2));
        float mn0 = fmaxf(m0, mt0), mn1 = fmaxf(m1, mt1);
        float al0 = ex2f((m0 - mn0) * L2E), al1 = ex2f((m1 - mn1) * L2E);
        float s0 = 0.f, s1 = 0.f;
#pragma unroll
        for (int nt = 0; nt < 8; nt++) {
            sc[nt][0] = ex2f((sc[nt][0] - mn0) * L2E);
            sc[nt][1] = ex2f((sc[nt][1] - mn0) * L2E);
            sc[nt][2] = ex2f((sc[nt][2] - mn1) * L2E);
            sc[nt][3] = ex2f((sc[nt][3] - mn1) * L2E);
            s0 += sc[nt][0] + sc[nt][1];
            s1 += sc[nt][2] + sc[nt][3];
        }
        s0 += __shfl_xor_sync(0xffffffffu, s0, 1);
        s0 += __shfl_xor_sync(0xffffffffu, s0, 2);
        s1 += __shfl_xor_sync(0xffffffffu, s1, 1);
        s1 += __shfl_xor_sync(0xffffffffu, s1, 2);
        l0 = l0 * al0 + s0; l1 = l1 * al1 + s1;
        m0 = mn0; m1 = mn1;
#pragma unroll
        for (int nt = 0; nt < 8; nt++) {
            o[nt][0] *= al0; o[nt][1] *= al0;
            o[nt][2] *= al1; o[nt][3] *= al1;
        }
        // ---- O += P V ----
#pragma unroll
        for (int sk = 0; sk < 4; sk++) {
            float* t0 = sc[2 * sk];
            float* t1 = sc[2 * sk + 1];
            uint32_t pah0 = pkbf(t0[0], t0[1]), pah1 = pkbf(t0[2], t0[3]);
            uint32_t pah2 = pkbf(t1[0], t1[1]), pah3 = pkbf(t1[2], t1[3]);
            uint32_t pal0 = pkbf(t0[0] - bfr(t0[0]), t0[1] - bfr(t0[1]));
            uint32_t pal1 = pkbf(t0[2] - bfr(t0[2]), t0[3] - bfr(t0[3]));
            uint32_t pal2 = pkbf(t1[0] - bfr(t1[0]), t1[1] - bfr(t1[1]));
            uint32_t pal3 = pkbf(t1[2] - bfr(t1[2]), t1[3] - bfr(t1[3]));
#pragma unroll
            for (int hp = 0; hp < 4; hp++) {
                uint32_t rs = sk * 16 + (lane & 7) + ((lane >> 3) & 1) * 8;
                uint32_t hb = (hp * 16 + (lane >> 4) * 8) * 2;
                uint4 vh, vl;
                ldsm4t(vh, Kb + 18432 + rs * 144 + hb);
                ldsm4t(vl, Kb + 27648 + rs * 144 + hb);
                mmabf_a(o[hp * 2], pah0, pah1, pah2, pah3, vh.x, vh.y);
                mmabf_a(o[hp * 2 + 1], pah0, pah1, pah2, pah3, vh.z, vh.w);
                mmabf_a(o[hp * 2], pal0, pal1, pal2, pal3, vh.x, vh.y);
                mmabf_a(o[hp * 2 + 1], pal0, pal1, pal2, pal3, vh.z, vh.w);
                mmabf_a(o[hp * 2], pah0, pah1, pah2, pah3, vl.x, vl.y);
                mmabf_a(o[hp * 2 + 1], pah0, pah1, pah2, pah3, vl.z, vl.w);
            }
        }
    }
    // ---- epilogue ----
    float i0 = 1.f / l0, i1 = 1.f / l1;
#pragma unroll
    for (int nt = 0; nt < 8; nt++) {
        int col = nt * 8 + (lane & 3) * 2;
        float2 v0 = {o[nt][0] * i0, o[nt][1] * i0};
        float2 v1 = {o[nt][2] * i1, o[nt][3] * i1};
        *(float2*)(out + ((size_t)b * TT + gr0) * 64 + col) = v0;
        *(float2*)(out + ((size_t)b * TT + gr0 + 8) * 64 + col) = v1;
    }
}

// ---------------------------------------------------------------------------
extern "C" void kernel_launch(void* const* d_in, const int* in_sizes, int n_in,
                              void* d_out, int out_size) {
    const float* x  = (const float*)d_in[0];
    const float* Wq = (const float*)d_in[1];
    const float* Wk = (const float*)d_in[2];
    const float* Wv = (const float*)d_in[3];
    float* out = (float*)d_out;

    cudaFuncSetAttribute(proj_kernel, cudaFuncAttributeMaxDynamicSharedMemorySize, PRJ_SMEM);
    cudaFuncSetAttribute(attn_kernel, cudaFuncAttributeMaxDynamicSharedMemorySize, ATN_SMEM);

    prep_kernel<<<192, 256>>>(Wq, Wk, Wv);
    proj_kernel<<<MROWS / 128, 256, PRJ_SMEM>>>(x);
    attn_kernel<<<BB * (TT / 64), 128, ATN_SMEM>>>(out);
}

// round 6
// speedup vs baseline: 4.4724x; 1.2141x over previous
#include <cuda_runtime.h>
#include <cuda_bf16.h>
#include <cstdint>

#define BB 4
#define TT 4096
#define CC 1024
#define HH 64
constexpr int MROWS = BB * TT;  // 16384

// ---------------- device scratch (q scaled by 1/32; all [m][h] bf16) -------
__device__ __nv_bfloat16 g_wth[192 * CC], g_wtl[192 * CC];   // W^T hi/lo [n][c]
__device__ __nv_bfloat16 g_qh[MROWS * HH], g_ql[MROWS * HH];
__device__ __nv_bfloat16 g_kh[MROWS * HH], g_kl[MROWS * HH];
__device__ __nv_bfloat16 g_vh[MROWS * HH], g_vl[MROWS * HH];
// split-KV partials: 256 q-tiles x 2 halves
__device__ float g_po[512 * 64 * 64];   // unnormalized O
__device__ float g_pm[512 * 64];        // row max
__device__ float g_pl[512 * 64];        // row sum

// ---------------- helpers ----------------
__device__ __forceinline__ uint32_t smem_u32(const void* p) {
    uint32_t a;
    asm("{ .reg .u64 t; cvta.to.shared.u64 t, %1; cvt.u32.u64 %0, t; }" : "=r"(a) : "l"(p));
    return a;
}
__device__ __forceinline__ uint32_t pkbf(float lo, float hi) {  // bf16x2 {lo,hi}
    uint32_t d;
    asm("cvt.rn.bf16x2.f32 %0, %1, %2;" : "=r"(d) : "f"(hi), "f"(lo));
    return d;
}
__device__ __forceinline__ float bfr(float x) { return __bfloat162float(__float2bfloat16_rn(x)); }
__device__ __forceinline__ float ex2f(float x) {
    float r; asm("ex2.approx.ftz.f32 %0, %1;" : "=f"(r) : "f"(x)); return r;
}
__device__ __forceinline__ void ldsm4(uint4& d, uint32_t a) {
    asm volatile("ldmatrix.sync.aligned.m8n8.x4.shared.b16 {%0,%1,%2,%3}, [%4];"
                 : "=r"(d.x), "=r"(d.y), "=r"(d.z), "=r"(d.w) : "r"(a));
}
__device__ __forceinline__ void ldsm4t(uint4& d, uint32_t a) {
    asm volatile("ldmatrix.sync.aligned.m8n8.x4.trans.shared.b16 {%0,%1,%2,%3}, [%4];"
                 : "=r"(d.x), "=r"(d.y), "=r"(d.z), "=r"(d.w) : "r"(a));
}
__device__ __forceinline__ void mmabf(float* c, const uint4& a, uint32_t b0, uint32_t b1) {
    asm volatile("mma.sync.aligned.m16n8k16.row.col.f32.bf16.bf16.f32 "
                 "{%0,%1,%2,%3}, {%4,%5,%6,%7}, {%8,%9}, {%0,%1,%2,%3};"
                 : "+f"(c[0]), "+f"(c[1]), "+f"(c[2]), "+f"(c[3])
                 : "r"(a.x), "r"(a.y), "r"(a.z), "r"(a.w), "r"(b0), "r"(b1));
}
__device__ __forceinline__ void mmabf_a(float* c, uint32_t a0, uint32_t a1, uint32_t a2,
                                        uint32_t a3, uint32_t b0, uint32_t b1) {
    asm volatile("mma.sync.aligned.m16n8k16.row.col.f32.bf16.bf16.f32 "
                 "{%0,%1,%2,%3}, {%4,%5,%6,%7}, {%8,%9}, {%0,%1,%2,%3};"
                 : "+f"(c[0]), "+f"(c[1]), "+f"(c[2]), "+f"(c[3])
                 : "r"(a0), "r"(a1), "r"(a2), "r"(a3), "r"(b0), "r"(b1));
}
#define CPA(dst, src)  asm volatile("cp.async.cg.shared.global [%0], [%1], 16;" :: "r"(dst), "l"(src))
#define CPCOMMIT()     asm volatile("cp.async.commit_group;" ::: "memory")
#define CPWAIT0()      asm volatile("cp.async.wait_group 0;" ::: "memory")

// ---------------------------------------------------------------------------
// Kernel 0: W^T hi/lo split, coalesced via smem transpose.
// 24 blocks x 256 thr; block handles 8 consecutive n rows of g_wt*.
// ---------------------------------------------------------------------------
__global__ __launch_bounds__(256) void prep_kernel(
    const float* __restrict__ Wq, const float* __restrict__ Wk,
    const float* __restrict__ Wv) {
    __shared__ float s[8][1032];
    const int tid = threadIdx.x;
    const int n0 = blockIdx.x * 8;
    const float* W = (n0 < 64) ? Wq : ((n0 < 128) ? Wk : Wv);
    const int col0 = n0 & 63;
    const int nn = tid & 7, cc = tid >> 3;  // cc: 0..31
    for (int c0 = 0; c0 < CC; c0 += 32)
        s[nn][c0 + cc] = W[(c0 + cc) * 64 + col0 + nn];
    __syncthreads();
    const int row = tid >> 5, lane = tid & 31;
    const int n = n0 + row;
    const float* sr = s[row];
    uint32_t* dh = (uint32_t*)g_wth + (size_t)n * 512;
    uint32_t* dl = (uint32_t*)g_wtl + (size_t)n * 512;
#pragma unroll
    for (int k = 0; k < 16; k++) {
        int c = 2 * lane + 64 * k;
        float a0 = sr[c], a1 = sr[c + 1];
        dh[lane + 32 * k] = pkbf(a0, a1);
        dl[lane + 32 * k] = pkbf(a0 - bfr(a0), a1 - bfr(a1));
    }
}

// ---------------------------------------------------------------------------
// Kernel 1: QKV projection, mma.sync bf16 3-term.
// Block tile 128(M) x 192(N), K chunks of 64. 8 warps = 4(M) x 2(N).
// ---------------------------------------------------------------------------
#define PRJ_ASTG 36864
#define PRJ_BOFF 73728
#define PRJ_BSTG 55296
#define PRJ_SMEM (PRJ_BOFF + 2 * PRJ_BSTG)   // 184320

__global__ __launch_bounds__(256) void proj_kernel(const float* __restrict__ x) {
    extern __shared__ char sm[];
    uint32_t sb = smem_u32(sm);
    const int tid = threadIdx.x;
    const int lane = tid & 31, wid = tid >> 5;
    const int wm = wid & 3, wn = wid >> 2;
    const int row0 = blockIdx.x * 128;
    const int arow = tid >> 1, acs = (tid & 1) * 32;

    float c[2][12][4];
#pragma unroll
    for (int i = 0; i < 2; i++)
#pragma unroll
        for (int t = 0; t < 12; t++)
#pragma unroll
            for (int e = 0; e < 4; e++) c[i][t][e] = 0.f;

    float4 xr[8];
    {
        const float4* s = (const float4*)(x + (size_t)(row0 + arow) * CC + acs);
#pragma unroll
        for (int g = 0; g < 8; g++) xr[g] = s[g];
    }
    {
        uint32_t Bb = sb + PRJ_BOFF;
#pragma unroll
        for (int e = 0; e < 12; e++) {
            int idx = tid + (e % 6) * 256;
            int row = idx >> 3, j = idx & 7;
            const char* src = (e < 6 ? (const char*)g_wth : (const char*)g_wtl)
                              + (size_t)row * 2048 + j * 16;
            CPA(Bb + (e < 6 ? 0u : (uint32_t)PRJ_BSTG / 2) + row * 144 + j * 16, src);
        }
        CPCOMMIT();
    }

    for (int kc = 0; kc < 16; kc++) {
        const uint32_t Ab = sb + (kc & 1) * PRJ_ASTG;
        const uint32_t Bb = sb + PRJ_BOFF + (kc & 1) * PRJ_BSTG;
        {
            char* dst = sm + (kc & 1) * PRJ_ASTG + arow * 144 + acs * 2;
#pragma unroll
            for (int g = 0; g < 4; g++) {
                float e[8] = {xr[2 * g].x, xr[2 * g].y, xr[2 * g].z, xr[2 * g].w,
                              xr[2 * g + 1].x, xr[2 * g + 1].y, xr[2 * g + 1].z, xr[2 * g + 1].w};
                uint4 H, L;
                uint32_t* hp = (uint32_t*)&H;
                uint32_t* lp = (uint32_t*)&L;
#pragma unroll
                for (int q = 0; q < 4; q++) {
                    float a0 = e[2 * q], a1 = e[2 * q + 1];
                    hp[q] = pkbf(a0, a1);
                    lp[q] = pkbf(a0 - bfr(a0), a1 - bfr(a1));
                }
                *(uint4*)(dst + g * 16) = H;
                *(uint4*)(dst + 18432 + g * 16) = L;
            }
        }
        if (kc < 15) {
            const float4* s = (const float4*)(x + (size_t)(row0 + arow) * CC + (kc + 1) * 64 + acs);
#pragma unroll
            for (int g = 0; g < 8; g++) xr[g] = s[g];
        }
        CPWAIT0();
        __syncthreads();
        if (kc < 15) {
            uint32_t Bn = sb + PRJ_BOFF + ((kc + 1) & 1) * PRJ_BSTG;
            int k0 = (kc + 1) * 64;
#pragma unroll
            for (int e = 0; e < 12; e++) {
                int idx = tid + (e % 6) * 256;
                int row = idx >> 3, j = idx & 7;
                const char* src = (e < 6 ? (const char*)g_wth : (const char*)g_wtl)
                                  + (size_t)row * 2048 + k0 * 2 + j * 16;
                CPA(Bn + (e < 6 ? 0u : (uint32_t)PRJ_BSTG / 2) + row * 144 + j * 16, src);
            }
            CPCOMMIT();
        }
#pragma unroll
        for (int ks = 0; ks < 4; ks++) {
            uint4 ah[2], al[2];
#pragma unroll
            for (int i = 0; i < 2; i++) {
                uint32_t r = wm * 32 + i * 16 + (lane & 15);
                uint32_t cb = ks * 32 + (lane >> 4) * 16;
                ldsm4(ah[i], Ab + r * 144 + cb);
                ldsm4(al[i], Ab + 18432 + r * 144 + cb);
            }
#pragma unroll
            for (int np = 0; np < 6; np++) {
                uint32_t rn = wn * 96 + np * 16 + (lane & 7) + ((lane >> 4) << 3);
                uint32_t cb = ks * 32 + ((lane >> 3) & 1) * 16;
                uint4 bh, bl;
                ldsm4(bh, Bb + rn * 144 + cb);
                ldsm4(bl, Bb + PRJ_BSTG / 2 + rn * 144 + cb);
#pragma unroll
                for (int i = 0; i < 2; i++) {
                    mmabf(c[i][np * 2], ah[i], bh.x, bh.y);
                    mmabf(c[i][np * 2 + 1], ah[i], bh.z, bh.w);
                    mmabf(c[i][np * 2], al[i], bh.x, bh.y);
                    mmabf(c[i][np * 2 + 1], al[i], bh.z, bh.w);
                    mmabf(c[i][np * 2], ah[i], bl.x, bl.y);
                    mmabf(c[i][np * 2 + 1], ah[i], bl.z, bl.w);
                }
            }
        }
    }
#pragma unroll
    for (int i = 0; i < 2; i++) {
#pragma unroll
        for (int nt = 0; nt < 12; nt++) {
            int n = wn * 96 + nt * 8 + (lane & 3) * 2;
            int tgt = n >> 6, nn = n & 63;
            float sc = (tgt == 0) ? 0.03125f : 1.0f;
            uint32_t* dh = (uint32_t*)((tgt == 0) ? g_qh : (tgt == 1) ? g_kh : g_vh);
            uint32_t* dl = (uint32_t*)((tgt == 0) ? g_ql : (tgt == 1) ? g_kl : g_vl);
#pragma unroll
            for (int h = 0; h < 2; h++) {
                int m = row0 + wm * 32 + i * 16 + (lane >> 2) + h * 8;
                float a0 = c[i][nt][2 * h] * sc, a1 = c[i][nt][2 * h + 1] * sc;
                dh[(size_t)m * 32 + nn / 2] = pkbf(a0, a1);
                dl[(size_t)m * 32 + nn / 2] = pkbf(a0 - bfr(a0), a1 - bfr(a1));
            }
        }
    }
}

// ---------------------------------------------------------------------------
// Kernel 2: flash attention, split-KV (2 halves per q-tile) for load balance.
// BQ=BK=64, 4 warps.  Partials (unnormalized O, m, l) -> g_p*.
// grid 512: bid -> qi descending (longest first), b, half.
// ---------------------------------------------------------------------------
#define ATN_STG 36864
#define ATN_SMEM (2 * ATN_STG)

__global__ __launch_bounds__(128) void attn_kernel() {
    extern __shared__ char sm[];
    uint32_t sb = smem_u32(sm);
    const int tid = threadIdx.x;
    const int lane = tid & 31, wid = tid >> 5;
    const int bid = blockIdx.x;
    const int qq = 63 - (bid >> 3);
    const int b = (bid >> 1) & 3;
    const int half = bid & 1;
    const int nk = qq + 1;
    const int hsp = (nk + 1) >> 1;
    const int kt0 = half ? hsp : 0;
    const int kt1 = half ? nk : hsp;
    const int pidx = ((b << 6) | qq) * 2 + half;
    const int pbase = pidx * 4096;
    const float L2E = 1.4426950408889634f;

    if (kt0 >= kt1) {  // empty half (qi=0, half 1): neutral partials
        for (int i = tid; i < 4096; i += 128) g_po[pbase + i] = 0.f;
        if (tid < 64) { g_pm[pidx * 64 + tid] = -1e30f; g_pl[pidx * 64 + tid] = 0.f; }
        return;
    }

    // stage Q (64x64 hi/lo) into stage-0 K slots via cp.async
    {
#pragma unroll
        for (int e = 0; e < 8; e++) {
            int rem = tid + (e & 3) * 128;
            int row = rem >> 3, j = rem & 7;
            const char* src = (e < 4 ? (const char*)g_qh : (const char*)g_ql)
                              + ((size_t)(b * TT + qq * 64 + row)) * 128 + j * 16;
            CPA(sb + (e < 4 ? 0 : 9216) + row * 144 + j * 16, src);
        }
        CPCOMMIT();
        CPWAIT0();
        __syncthreads();
    }
    uint4 qh[4], ql[4];
#pragma unroll
    for (int ks = 0; ks < 4; ks++) {
        uint32_t r = wid * 16 + (lane & 15);
        uint32_t cb = ks * 32 + (lane >> 4) * 16;
        ldsm4(qh[ks], sb + r * 144 + cb);
        ldsm4(ql[ks], sb + 9216 + r * 144 + cb);
    }
    __syncthreads();

    // prefetch K/V tile kt0
#pragma unroll
    for (int e = 0; e < 16; e++) {
        int arr = e >> 2;
        int rem = tid + (e & 3) * 128;
        int row = rem >> 3, j = rem & 7;
        const char* src = (arr == 0 ? (const char*)g_kh : arr == 1 ? (const char*)g_kl
                           : arr == 2 ? (const char*)g_vh : (const char*)g_vl)
                          + ((size_t)(b * TT + kt0 * 64 + row)) * 128 + j * 16;
        CPA(sb + (kt0 & 1) * ATN_STG + arr * 9216 + row * 144 + j * 16, src);
    }
    CPCOMMIT();

    float o[8][4];
#pragma unroll
    for (int t = 0; t < 8; t++)
#pragma unroll
        for (int e = 0; e < 4; e++) o[t][e] = 0.f;
    float m0 = -1e30f, m1 = -1e30f, l0 = 0.f, l1 = 0.f;

    const int r0 = wid * 16 + (lane >> 2);       // local row in tile
    const int gr0 = qq * 64 + r0;                // global row (for masking)

    for (int kt = kt0; kt < kt1; kt++) {
        CPWAIT0();
        __syncthreads();
        const uint32_t Kb = sb + (kt & 1) * ATN_STG;
        if (kt + 1 < kt1) {
            uint32_t Nb = sb + ((kt + 1) & 1) * ATN_STG;
#pragma unroll
            for (int e = 0; e < 16; e++) {
                int arr = e >> 2;
                int rem = tid + (e & 3) * 128;
                int row = rem >> 3, j = rem & 7;
                const char* src = (arr == 0 ? (const char*)g_kh : arr == 1 ? (const char*)g_kl
                                   : arr == 2 ? (const char*)g_vh : (const char*)g_vl)
                                  + ((size_t)(b * TT + (kt + 1) * 64 + row)) * 128 + j * 16;
                CPA(Nb + arr * 9216 + row * 144 + j * 16, src);
            }
            CPCOMMIT();
        }

        // ---- S = Q K^T ----
        float sc[8][4];
#pragma unroll
        for (int t = 0; t < 8; t++)
#pragma unroll
            for (int e = 0; e < 4; e++) sc[t][e] = 0.f;
#pragma unroll
        for (int ks = 0; ks < 4; ks++) {
#pragma unroll
            for (int np = 0; np < 4; np++) {
                uint32_t rn = np * 16 + (lane & 7) + ((lane >> 4) << 3);
                uint32_t cb = ks * 32 + ((lane >> 3) & 1) * 16;
                uint4 bh, bl;
                ldsm4(bh, Kb + rn * 144 + cb);
                ldsm4(bl, Kb + 9216 + rn * 144 + cb);
                mmabf(sc[np * 2], qh[ks], bh.x, bh.y);
                mmabf(sc[np * 2 + 1], qh[ks], bh.z, bh.w);
                mmabf(sc[np * 2], ql[ks], bh.x, bh.y);
                mmabf(sc[np * 2 + 1], ql[ks], bh.z, bh.w);
                mmabf(sc[np * 2], qh[ks], bl.x, bl.y);
                mmabf(sc[np * 2 + 1], qh[ks], bl.z, bl.w);
            }
        }
        if (kt == qq) {
#pragma unroll
            for (int nt = 0; nt < 8; nt++) {
                int gc = kt * 64 + nt * 8 + (lane & 3) * 2;
                if (gc > gr0) sc[nt][0] = -1e30f;
                if (gc + 1 > gr0) sc[nt][1] = -1e30f;
                if (gc > gr0 + 8) sc[nt][2] = -1e30f;
                if (gc + 1 > gr0 + 8) sc[nt][3] = -1e30f;
            }
        }
        float mt0 = -1e30f, mt1 = -1e30f;
#pragma unroll
        for (int nt = 0; nt < 8; nt++) {
            mt0 = fmaxf(mt0, fmaxf(sc[nt][0], sc[nt][1]));
            mt1 = fmaxf(mt1, fmaxf(sc[nt][2], sc[nt][3]));
        }
        mt0 = fmaxf(mt0, __shfl_xor_sync(0xffffffffu, mt0, 1));
        mt0 = fmaxf(mt0, __shfl_xor_sync(0xffffffffu, mt0, 2));
        mt1 = fmaxf(mt1, __shfl_xor_sync(0xffffffffu, mt1, 1));
        mt1 = fmaxf(mt1, __shfl_xor_sync(0xffffffffu, mt1, 2));
        float mn0 = fmaxf(m0, mt0), mn1 = fmaxf(m1, mt1);
        float al0 = ex2f((m0 - mn0) * L2E), al1 = ex2f((m1 - mn1) * L2E);
        float s0 = 0.f, s1 = 0.f;
#pragma unroll
        for (int nt = 0; nt < 8; nt++) {
            sc[nt][0] = ex2f((sc[nt][0] - mn0) * L2E);
            sc[nt][1] = ex2f((sc[nt][1] - mn0) * L2E);
            sc[nt][2] = ex2f((sc[nt][2] - mn1) * L2E);
            sc[nt][3] = ex2f((sc[nt][3] - mn1) * L2E);
            s0 += sc[nt][0] + sc[nt][1];
            s1 += sc[nt][2] + sc[nt][3];
        }
        s0 += __shfl_xor_sync(0xffffffffu, s0, 1);
        s0 += __shfl_xor_sync(0xffffffffu, s0, 2);
        s1 += __shfl_xor_sync(0xffffffffu, s1, 1);
        s1 += __shfl_xor_sync(0xffffffffu, s1, 2);
        l0 = l0 * al0 + s0; l1 = l1 * al1 + s1;
        m0 = mn0; m1 = mn1;
#pragma unroll
        for (int nt = 0; nt < 8; nt++) {
            o[nt][0] *= al0; o[nt][1] *= al0;
            o[nt][2] *= al1; o[nt][3] *= al1;
        }
#pragma unroll
        for (int sk = 0; sk < 4; sk++) {
            float* t0 = sc[2 * sk];
            float* t1 = sc[2 * sk + 1];
            uint32_t pah0 = pkbf(t0[0], t0[1]), pah1 = pkbf(t0[2], t0[3]);
            uint32_t pah2 = pkbf(t1[0], t1[1]), pah3 = pkbf(t1[2], t1[3]);
            uint32_t pal0 = pkbf(t0[0] - bfr(t0[0]), t0[1] - bfr(t0[1]));
            uint32_t pal1 = pkbf(t0[2] - bfr(t0[2]), t0[3] - bfr(t0[3]));
            uint32_t pal2 = pkbf(t1[0] - bfr(t1[0]), t1[1] - bfr(t1[1]));
            uint32_t pal3 = pkbf(t1[2] - bfr(t1[2]), t1[3] - bfr(t1[3]));
#pragma unroll
            for (int hp = 0; hp < 4; hp++) {
                uint32_t rs = sk * 16 + (lane & 7) + ((lane >> 3) & 1) * 8;
                uint32_t hb = (hp * 16 + (lane >> 4) * 8) * 2;
                uint4 vh, vl;
                ldsm4t(vh, Kb + 18432 + rs * 144 + hb);
                ldsm4t(vl, Kb + 27648 + rs * 144 + hb);
                mmabf_a(o[hp * 2], pah0, pah1, pah2, pah3, vh.x, vh.y);
                mmabf_a(o[hp * 2 + 1], pah0, pah1, pah2, pah3, vh.z, vh.w);
                mmabf_a(o[hp * 2], pal0, pal1, pal2, pal3, vh.x, vh.y);
                mmabf_a(o[hp * 2 + 1], pal0, pal1, pal2, pal3, vh.z, vh.w);
                mmabf_a(o[hp * 2], pah0, pah1, pah2, pah3, vl.x, vl.y);
                mmabf_a(o[hp * 2 + 1], pah0, pah1, pah2, pah3, vl.z, vl.w);
            }
        }
    }
    // ---- write partials (unnormalized) ----
#pragma unroll
    for (int nt = 0; nt < 8; nt++) {
        int col = nt * 8 + (lane & 3) * 2;
        *(float2*)(g_po + pbase + r0 * 64 + col) = make_float2(o[nt][0], o[nt][1]);
        *(float2*)(g_po + pbase + (r0 + 8) * 64 + col) = make_float2(o[nt][2], o[nt][3]);
    }
    if ((lane & 3) == 0) {
        g_pm[pidx * 64 + r0] = m0;     g_pl[pidx * 64 + r0] = l0;
        g_pm[pidx * 64 + r0 + 8] = m1; g_pl[pidx * 64 + r0 + 8] = l1;
    }
}

// ---------------------------------------------------------------------------
// Kernel 3: merge two halves per q-tile, normalize, write output.
// ---------------------------------------------------------------------------
__global__ __launch_bounds__(256) void merge_kernel(float* __restrict__ out) {
    const int qt = blockIdx.x;           // (b<<6)|qi
    const int b = qt >> 6, qi = qt & 63;
    const int tid = threadIdx.x;
    const int r = tid >> 2, seg = (tid & 3) * 16;
    const int p0 = qt * 2, p1 = qt * 2 + 1;
    const float L2E = 1.4426950408889634f;
    float m1 = g_pm[p0 * 64 + r], m2 = g_pm[p1 * 64 + r];
    float l1 = g_pl[p0 * 64 + r], l2 = g_pl[p1 * 64 + r];
    float m = fmaxf(m1, m2);
    float w1 = ex2f((m1 - m) * L2E), w2 = ex2f((m2 - m) * L2E);
    float inv = 1.f / (l1 * w1 + l2 * w2);
    const float4* o1 = (const float4*)(g_po + p0 * 4096 + r * 64 + seg);
    const float4* o2 = (const float4*)(g_po + p1 * 4096 + r * 64 + seg);
    float4* dst = (float4*)(out + ((size_t)b * TT + qi * 64 + r) * 64 + seg);
#pragma unroll
    for (int g = 0; g < 4; g++) {
        float4 a = o1[g], c = o2[g];
        float4 v;
        v.x = (a.x * w1 + c.x * w2) * inv;
        v.y = (a.y * w1 + c.y * w2) * inv;
        v.z = (a.z * w1 + c.z * w2) * inv;
        v.w = (a.w * w1 + c.w * w2) * inv;
        dst[g] = v;
    }
}

// ---------------------------------------------------------------------------
extern "C" void kernel_launch(void* const* d_in, const int* in_sizes, int n_in,
                              void* d_out, int out_size) {
    const float* x  = (const float*)d_in[0];
    const float* Wq = (const float*)d_in[1];
    const float* Wk = (const float*)d_in[2];
    const float* Wv = (const float*)d_in[3];
    float* out = (float*)d_out;

    cudaFuncSetAttribute(proj_kernel, cudaFuncAttributeMaxDynamicSharedMemorySize, PRJ_SMEM);
    cudaFuncSetAttribute(attn_kernel, cudaFuncAttributeMaxDynamicSharedMemorySize, ATN_SMEM);

    prep_kernel<<<24, 256>>>(Wq, Wk, Wv);
    proj_kernel<<<MROWS / 128, 256, PRJ_SMEM>>>(x);
    attn_kernel<<<512, 128, ATN_SMEM>>>();
    merge_kernel<<<256, 256>>>(out);
}

// round 12
// speedup vs baseline: 4.7558x; 1.0634x over previous
#include <cuda_runtime.h>
#include <cuda_bf16.h>
#include <cuda_fp16.h>
#include <cstdint>

#define BB 4
#define TT 4096
#define CC 1024
#define HH 64
constexpr int MROWS = BB * TT;  // 16384

// ---------------- device scratch (q scaled by 1/32) ----------------
__device__ __nv_bfloat16 g_wth[192 * CC], g_wtl[192 * CC];   // W^T hi/lo [n][c]
__device__ __nv_bfloat16 g_qh[MROWS * HH], g_ql[MROWS * HH];
__device__ __nv_bfloat16 g_kh[MROWS * HH], g_kl[MROWS * HH];
__device__ __half        g_v[MROWS * HH];                    // V single fp16
// split-KV partials: 256 q-tiles x up to 4 chunks of 16 k-tiles
__device__ float g_po[1024 * 64 * 64];
__device__ float g_pm[1024 * 64];
__device__ float g_pl[1024 * 64];

// ---------------- helpers ----------------
__device__ __forceinline__ uint32_t smem_u32(const void* p) {
    uint32_t a;
    asm("{ .reg .u64 t; cvta.to.shared.u64 t, %1; cvt.u32.u64 %0, t; }" : "=r"(a) : "l"(p));
    return a;
}
__device__ __forceinline__ uint32_t pkbf(float lo, float hi) {  // bf16x2 {lo,hi}
    uint32_t d;
    asm("cvt.rn.bf16x2.f32 %0, %1, %2;" : "=r"(d) : "f"(hi), "f"(lo));
    return d;
}
__device__ __forceinline__ uint32_t pkhf(float lo, float hi) {  // f16x2 {lo,hi}
    uint32_t d;
    asm("cvt.rn.f16x2.f32 %0, %1, %2;" : "=r"(d) : "f"(hi), "f"(lo));
    return d;
}
__device__ __forceinline__ float bfr(float x) { return __bfloat162float(__float2bfloat16_rn(x)); }
__device__ __forceinline__ float hfr(float x) { return __half2float(__float2half_rn(x)); }
__device__ __forceinline__ float ex2f(float x) {
    float r; asm("ex2.approx.ftz.f32 %0, %1;" : "=f"(r) : "f"(x)); return r;
}
__device__ __forceinline__ void ldsm4(uint4& d, uint32_t a) {
    asm volatile("ldmatrix.sync.aligned.m8n8.x4.shared.b16 {%0,%1,%2,%3}, [%4];"
                 : "=r"(d.x), "=r"(d.y), "=r"(d.z), "=r"(d.w) : "r"(a));
}
__device__ __forceinline__ void ldsm4t(uint4& d, uint32_t a) {
    asm volatile("ldmatrix.sync.aligned.m8n8.x4.trans.shared.b16 {%0,%1,%2,%3}, [%4];"
                 : "=r"(d.x), "=r"(d.y), "=r"(d.z), "=r"(d.w) : "r"(a));
}
__device__ __forceinline__ void mmabf(float* c, const uint4& a, uint32_t b0, uint32_t b1) {
    asm volatile("mma.sync.aligned.m16n8k16.row.col.f32.bf16.bf16.f32 "
                 "{%0,%1,%2,%3}, {%4,%5,%6,%7}, {%8,%9}, {%0,%1,%2,%3};"
                 : "+f"(c[0]), "+f"(c[1]), "+f"(c[2]), "+f"(c[3])
                 : "r"(a.x), "r"(a.y), "r"(a.z), "r"(a.w), "r"(b0), "r"(b1));
}
__device__ __forceinline__ void mmahf_a(float* c, uint32_t a0, uint32_t a1, uint32_t a2,
                                        uint32_t a3, uint32_t b0, uint32_t b1) {
    asm volatile("mma.sync.aligned.m16n8k16.row.col.f32.f16.f16.f32 "
                 "{%0,%1,%2,%3}, {%4,%5,%6,%7}, {%8,%9}, {%0,%1,%2,%3};"
                 : "+f"(c[0]), "+f"(c[1]), "+f"(c[2]), "+f"(c[3])
                 : "r"(a0), "r"(a1), "r"(a2), "r"(a3), "r"(b0), "r"(b1));
}
#define CPA(dst, src)  asm volatile("cp.async.cg.shared.global [%0], [%1], 16;" :: "r"(dst), "l"(src))
#define CPCOMMIT()     asm volatile("cp.async.commit_group;" ::: "memory")
#define CPWAIT0()      asm volatile("cp.async.wait_group 0;" ::: "memory")

// ---------------------------------------------------------------------------
// Kernel 0: W^T hi/lo split (coalesced via smem transpose).
// ---------------------------------------------------------------------------
__global__ __launch_bounds__(256) void prep_kernel(
    const float* __restrict__ Wq, const float* __restrict__ Wk,
    const float* __restrict__ Wv) {
    __shared__ float s[8][1032];
    const int tid = threadIdx.x;
    const int n0 = blockIdx.x * 8;
    const float* W = (n0 < 64) ? Wq : ((n0 < 128) ? Wk : Wv);
    const int col0 = n0 & 63;
    const int nn = tid & 7, cc = tid >> 3;
    for (int c0 = 0; c0 < CC; c0 += 32)
        s[nn][c0 + cc] = W[(c0 + cc) * 64 + col0 + nn];
    __syncthreads();
    const int row = tid >> 5, lane = tid & 31;
    const int n = n0 + row;
    const float* sr = s[row];
    uint32_t* dh = (uint32_t*)g_wth + (size_t)n * 512;
    uint32_t* dl = (uint32_t*)g_wtl + (size_t)n * 512;
#pragma unroll
    for (int k = 0; k < 16; k++) {
        int c = 2 * lane + 64 * k;
        float a0 = sr[c], a1 = sr[c + 1];
        dh[lane + 32 * k] = pkbf(a0, a1);
        dl[lane + 32 * k] = pkbf(a0 - bfr(a0), a1 - bfr(a1));
    }
}

// ---------------------------------------------------------------------------
// Kernel 1: QKV projection.  Block tile 128(M) x 96(N), grid (128, 2).
// A single-buffered (36864), B double-buffered (2 x 27648) => 92160 B smem,
// 2 CTAs/SM.  8 warps = 4(M) x 2(N, 48 cols each).
// ---------------------------------------------------------------------------
#define PRJ_BOFF 36864
#define PRJ_BSTG 27648
#define PRJ_SMEM (PRJ_BOFF + 2 * PRJ_BSTG)   // 92160

__global__ __launch_bounds__(256, 2) void proj_kernel(const float* __restrict__ x) {
    extern __shared__ char sm[];
    uint32_t sb = smem_u32(sm);
    const int tid = threadIdx.x;
    const int lane = tid & 31, wid = tid >> 5;
    const int wm = wid & 3, wn = wid >> 2;
    const int row0 = blockIdx.x * 128;
    const int ny = blockIdx.y;            // 0: n 0..95, 1: n 96..191
    const int arow = tid >> 1, acs = (tid & 1) * 32;

    float c[2][6][4];
#pragma unroll
    for (int i = 0; i < 2; i++)
#pragma unroll
        for (int t = 0; t < 6; t++)
#pragma unroll
            for (int e = 0; e < 4; e++) c[i][t][e] = 0.f;

    float4 xr[8];
    {
        const float4* s = (const float4*)(x + (size_t)(row0 + arow) * CC + acs);
#pragma unroll
        for (int g = 0; g < 8; g++) xr[g] = s[g];
    }
    // B chunk 0 -> stage 0
    {
        uint32_t Bb = sb + PRJ_BOFF;
#pragma unroll
        for (int e = 0; e < 6; e++) {
            int idx = tid + (e % 3) * 256;
            int row = idx >> 3, j = idx & 7;
            const char* src = (e < 3 ? (const char*)g_wth : (const char*)g_wtl)
                              + (size_t)(ny * 96 + row) * 2048 + j * 16;
            CPA(Bb + (e < 3 ? 0u : 13824u) + row * 144 + j * 16, src);
        }
        CPCOMMIT();
    }

    for (int kc = 0; kc < 16; kc++) {
        const uint32_t Ab = sb;
        const uint32_t Bb = sb + PRJ_BOFF + (kc & 1) * PRJ_BSTG;
        __syncthreads();  // prev mma done reading A
        {
            char* dst = sm + arow * 144 + acs * 2;
#pragma unroll
            for (int g = 0; g < 4; g++) {
                float e[8] = {xr[2 * g].x, xr[2 * g].y, xr[2 * g].z, xr[2 * g].w,
                              xr[2 * g + 1].x, xr[2 * g + 1].y, xr[2 * g + 1].z, xr[2 * g + 1].w};
                uint4 H, L;
                uint32_t* hp = (uint32_t*)&H;
                uint32_t* lp = (uint32_t*)&L;
#pragma unroll
                for (int q = 0; q < 4; q++) {
                    float a0 = e[2 * q], a1 = e[2 * q + 1];
                    hp[q] = pkbf(a0, a1);
                    lp[q] = pkbf(a0 - bfr(a0), a1 - bfr(a1));
                }
                *(uint4*)(dst + g * 16) = H;
                *(uint4*)(dst + 18432 + g * 16) = L;
            }
        }
        if (kc < 15) {
            const float4* s = (const float4*)(x + (size_t)(row0 + arow) * CC + (kc + 1) * 64 + acs);
#pragma unroll
            for (int g = 0; g < 8; g++) xr[g] = s[g];
        }
        CPWAIT0();
        __syncthreads();  // A visible + B(kc) ready
        if (kc < 15) {
            uint32_t Bn = sb + PRJ_BOFF + ((kc + 1) & 1) * PRJ_BSTG;
            int k0 = (kc + 1) * 64;
#pragma unroll
            for (int e = 0; e < 6; e++) {
                int idx = tid + (e % 3) * 256;
                int row = idx >> 3, j = idx & 7;
                const char* src = (e < 3 ? (const char*)g_wth : (const char*)g_wtl)
                                  + (size_t)(ny * 96 + row) * 2048 + k0 * 2 + j * 16;
                CPA(Bn + (e < 3 ? 0u : 13824u) + row * 144 + j * 16, src);
            }
            CPCOMMIT();
        }
#pragma unroll
        for (int ks = 0; ks < 4; ks++) {
            uint4 ah[2], al[2];
#pragma unroll
            for (int i = 0; i < 2; i++) {
                uint32_t r = wm * 32 + i * 16 + (lane & 15);
                uint32_t cb = ks * 32 + (lane >> 4) * 16;
                ldsm4(ah[i], Ab + r * 144 + cb);
                ldsm4(al[i], Ab + 18432 + r * 144 + cb);
            }
#pragma unroll
            for (int np = 0; np < 3; np++) {
                uint32_t rn = wn * 48 + np * 16 + (lane & 7) + ((lane >> 4) << 3);
                uint32_t cb = ks * 32 + ((lane >> 3) & 1) * 16;
                uint4 bh, bl;
                ldsm4(bh, Bb + rn * 144 + cb);
                ldsm4(bl, Bb + 13824 + rn * 144 + cb);
#pragma unroll
                for (int i = 0; i < 2; i++) {
                    mmabf(c[i][np * 2], ah[i], bh.x, bh.y);
                    mmabf(c[i][np * 2 + 1], ah[i], bh.z, bh.w);
                    mmabf(c[i][np * 2], al[i], bh.x, bh.y);
                    mmabf(c[i][np * 2 + 1], al[i], bh.z, bh.w);
                    mmabf(c[i][np * 2], ah[i], bl.x, bl.y);
                    mmabf(c[i][np * 2 + 1], ah[i], bl.z, bl.w);
                }
            }
        }
    }
    // epilogue: route q (bf16 hi/lo, x1/32), k (bf16 hi/lo), v (fp16 single)
#pragma unroll
    for (int i = 0; i < 2; i++) {
#pragma unroll
        for (int nt = 0; nt < 6; nt++) {
            int n = ny * 96 + wn * 48 + nt * 8 + (lane & 3) * 2;
            int tgt = n >> 6, nn = n & 63;
#pragma unroll
            for (int h = 0; h < 2; h++) {
                int m = row0 + wm * 32 + i * 16 + (lane >> 2) + h * 8;
                float a0 = c[i][nt][2 * h], a1 = c[i][nt][2 * h + 1];
                if (tgt == 0) {
                    a0 *= 0.03125f; a1 *= 0.03125f;
                    ((uint32_t*)g_qh)[(size_t)m * 32 + nn / 2] = pkbf(a0, a1);
                    ((uint32_t*)g_ql)[(size_t)m * 32 + nn / 2] =
                        pkbf(a0 - bfr(a0), a1 - bfr(a1));
                } else if (tgt == 1) {
                    ((uint32_t*)g_kh)[(size_t)m * 32 + nn / 2] = pkbf(a0, a1);
                    ((uint32_t*)g_kl)[(size_t)m * 32 + nn / 2] =
                        pkbf(a0 - bfr(a0), a1 - bfr(a1));
                } else {
                    ((uint32_t*)g_v)[(size_t)m * 32 + nn / 2] = pkhf(a0, a1);
                }
            }
        }
    }
}

// ---------------------------------------------------------------------------
// Kernel 2: flash attention, split-KV chunks of 16 k-tiles.
// BQ=BK=64, 4 warps.  QK bf16 3-term; PV fp16 2-term (P hi/lo, V single).
// smem stage = Kh 9216 | Kl 9216 | V 9216 = 27648, 2 stages => 4 CTAs/SM.
// grid 1024: g=bid>>2 -> (qi desc, b), c=bid&3.
// ---------------------------------------------------------------------------
#define ATN_STG 27648
#define ATN_SMEM (2 * ATN_STG)

__global__ __launch_bounds__(128, 4) void attn_kernel() {
    extern __shared__ char sm[];
    uint32_t sb = smem_u32(sm);
    const int tid = threadIdx.x;
    const int lane = tid & 31, wid = tid >> 5;
    const int bid = blockIdx.x;
    const int g = bid >> 2;
    const int qq = 63 - (g >> 2);
    const int b = g & 3;
    const int ch = bid & 3;
    const int nk = qq + 1;
    const int kt0 = ch * 16;
    const int kt1 = (kt0 + 16 < nk) ? kt0 + 16 : nk;
    if (kt0 >= nk) return;  // empty chunk
    const int pidx = (((b << 6) | qq) << 2) | ch;
    const int pbase = pidx * 4096;
    const float L2E = 1.4426950408889634f;

    // stage Q (64x64 hi/lo) into stage-0 K slots
    {
#pragma unroll
        for (int e = 0; e < 8; e++) {
            int rem = tid + (e & 3) * 128;
            int row = rem >> 3, j = rem & 7;
            const char* src = (e < 4 ? (const char*)g_qh : (const char*)g_ql)
                              + ((size_t)(b * TT + qq * 64 + row)) * 128 + j * 16;
            CPA(sb + (e < 4 ? 0 : 9216) + row * 144 + j * 16, src);
        }
        CPCOMMIT();
        CPWAIT0();
        __syncthreads();
    }
    uint4 qh[4], ql[4];
#pragma unroll
    for (int ks = 0; ks < 4; ks++) {
        uint32_t r = wid * 16 + (lane & 15);
        uint32_t cb = ks * 32 + (lane >> 4) * 16;
        ldsm4(qh[ks], sb + r * 144 + cb);
        ldsm4(ql[ks], sb + 9216 + r * 144 + cb);
    }
    __syncthreads();

    // prefetch K/V tile kt0
#pragma unroll
    for (int e = 0; e < 12; e++) {
        int arr = e >> 2;
        int rem = tid + (e & 3) * 128;
        int row = rem >> 3, j = rem & 7;
        const char* src = (arr == 0 ? (const char*)g_kh : arr == 1 ? (const char*)g_kl
                           : (const char*)g_v)
                          + ((size_t)(b * TT + kt0 * 64 + row)) * 128 + j * 16;
        CPA(sb + (kt0 & 1) * ATN_STG + arr * 9216 + row * 144 + j * 16, src);
    }
    CPCOMMIT();

    float o[8][4];
#pragma unroll
    for (int t = 0; t < 8; t++)
#pragma unroll
        for (int e = 0; e < 4; e++) o[t][e] = 0.f;
    float m0 = -1e30f, m1 = -1e30f, l0 = 0.f, l1 = 0.f;

    const int r0 = wid * 16 + (lane >> 2);
    const int gr0 = qq * 64 + r0;

    for (int kt = kt0; kt < kt1; kt++) {
        CPWAIT0();
        __syncthreads();
        const uint32_t Kb = sb + (kt & 1) * ATN_STG;
        if (kt + 1 < kt1) {
            uint32_t Nb = sb + ((kt + 1) & 1) * ATN_STG;
#pragma unroll
            for (int e = 0; e < 12; e++) {
                int arr = e >> 2;
                int rem = tid + (e & 3) * 128;
                int row = rem >> 3, j = rem & 7;
                const char* src = (arr == 0 ? (const char*)g_kh : arr == 1 ? (const char*)g_kl
                                   : (const char*)g_v)
                                  + ((size_t)(b * TT + (kt + 1) * 64 + row)) * 128 + j * 16;
                CPA(Nb + arr * 9216 + row * 144 + j * 16, src);
            }
            CPCOMMIT();
        }

        // ---- S = Q K^T (bf16 3-term) ----
        float sc[8][4];
#pragma unroll
        for (int t = 0; t < 8; t++)
#pragma unroll
            for (int e = 0; e < 4; e++) sc[t][e] = 0.f;
#pragma unroll
        for (int ks = 0; ks < 4; ks++) {
#pragma unroll
            for (int np = 0; np < 4; np++) {
                uint32_t rn = np * 16 + (lane & 7) + ((lane >> 4) << 3);
                uint32_t cb = ks * 32 + ((lane >> 3) & 1) * 16;
                uint4 bh, bl;
                ldsm4(bh, Kb + rn * 144 + cb);
                ldsm4(bl, Kb + 9216 + rn * 144 + cb);
                mmabf(sc[np * 2], qh[ks], bh.x, bh.y);
                mmabf(sc[np * 2 + 1], qh[ks], bh.z, bh.w);
                mmabf(sc[np * 2], ql[ks], bh.x, bh.y);
                mmabf(sc[np * 2 + 1], ql[ks], bh.z, bh.w);
                mmabf(sc[np * 2], qh[ks], bl.x, bl.y);
                mmabf(sc[np * 2 + 1], qh[ks], bl.z, bl.w);
            }
        }
        if (kt == qq) {
#pragma unroll
            for (int nt = 0; nt < 8; nt++) {
                int gc = kt * 64 + nt * 8 + (lane & 3) * 2;
                if (gc > gr0) sc[nt][0] = -1e30f;
                if (gc + 1 > gr0) sc[nt][1] = -1e30f;
                if (gc > gr0 + 8) sc[nt][2] = -1e30f;
                if (gc + 1 > gr0 + 8) sc[nt][3] = -1e30f;
            }
        }
        float mt0 = -1e30f, mt1 = -1e30f;
#pragma unroll
        for (int nt = 0; nt < 8; nt++) {
            mt0 = fmaxf(mt0, fmaxf(sc[nt][0], sc[nt][1]));
            mt1 = fmaxf(mt1, fmaxf(sc[nt][2], sc[nt][3]));
        }
        mt0 = fmaxf(mt0, __shfl_xor_sync(0xffffffffu, mt0, 1));
        mt0 = fmaxf(mt0, __shfl_xor_sync(0xffffffffu, mt0, 2));
        mt1 = fmaxf(mt1, __shfl_xor_sync(0xffffffffu, mt1, 1));
        mt1 = fmaxf(mt1, __shfl_xor_sync(0xffffffffu, mt1, 2));
        float mn0 = fmaxf(m0, mt0), mn1 = fmaxf(m1, mt1);
        float al0 = ex2f((m0 - mn0) * L2E), al1 = ex2f((m1 - mn1) * L2E);
        float s0 = 0.f, s1 = 0.f;
#pragma unroll
        for (int nt = 0; nt < 8; nt++) {
            sc[nt][0] = ex2f((sc[nt][0] - mn0) * L2E);
            sc[nt][1] = ex2f((sc[nt][1] - mn0) * L2E);
            sc[nt][2] = ex2f((sc[nt][2] - mn1) * L2E);
            sc[nt][3] = ex2f((sc[nt][3] - mn1) * L2E);
            s0 += sc[nt][0] + sc[nt][1];
            s1 += sc[nt][2] + sc[nt][3];
        }
        s0 += __shfl_xor_sync(0xffffffffu, s0, 1);
        s0 += __shfl_xor_sync(0xffffffffu, s0, 2);
        s1 += __shfl_xor_sync(0xffffffffu, s1, 1);
        s1 += __shfl_xor_sync(0xffffffffu, s1, 2);
        l0 = l0 * al0 + s0; l1 = l1 * al1 + s1;
        m0 = mn0; m1 = mn1;
#pragma unroll
        for (int nt = 0; nt < 8; nt++) {
            o[nt][0] *= al0; o[nt][1] *= al0;
            o[nt][2] *= al1; o[nt][3] *= al1;
        }
        // ---- O += P V (fp16: P hi/lo 2-term, V single) ----
#pragma unroll
        for (int sk = 0; sk < 4; sk++) {
            float* t0 = sc[2 * sk];
            float* t1 = sc[2 * sk + 1];
            uint32_t pah0 = pkhf(t0[0], t0[1]), pah1 = pkhf(t0[2], t0[3]);
            uint32_t pah2 = pkhf(t1[0], t1[1]), pah3 = pkhf(t1[2], t1[3]);
            uint32_t pal0 = pkhf(t0[0] - hfr(t0[0]), t0[1] - hfr(t0[1]));
            uint32_t pal1 = pkhf(t0[2] - hfr(t0[2]), t0[3] - hfr(t0[3]));
            uint32_t pal2 = pkhf(t1[0] - hfr(t1[0]), t1[1] - hfr(t1[1]));
            uint32_t pal3 = pkhf(t1[2] - hfr(t1[2]), t1[3] - hfr(t1[3]));
#pragma unroll
            for (int hp = 0; hp < 4; hp++) {
                uint32_t rs = sk * 16 + (lane & 7) + ((lane >> 3) & 1) * 8;
                uint32_t hb = (hp * 16 + (lane >> 4) * 8) * 2;
                uint4 v;
                ldsm4t(v, Kb + 18432 + rs * 144 + hb);
                mmahf_a(o[hp * 2], pah0, pah1, pah2, pah3, v.x, v.y);
                mmahf_a(o[hp * 2 + 1], pah0, pah1, pah2, pah3, v.z, v.w);
                mmahf_a(o[hp * 2], pal0, pal1, pal2, pal3, v.x, v.y);
                mmahf_a(o[hp * 2 + 1], pal0, pal1, pal2, pal3, v.z, v.w);
            }
        }
    }
    // ---- write partials ----
#pragma unroll
    for (int nt = 0; nt < 8; nt++) {
        int col = nt * 8 + (lane & 3) * 2;
        *(float2*)(g_po + pbase + r0 * 64 + col) = make_float2(o[nt][0], o[nt][1]);
        *(float2*)(g_po + pbase + (r0 + 8) * 64 + col) = make_float2(o[nt][2], o[nt][3]);
    }
    if ((lane & 3) == 0) {
        g_pm[pidx * 64 + r0] = m0;     g_pl[pidx * 64 + r0] = l0;
        g_pm[pidx * 64 + r0 + 8] = m1; g_pl[pidx * 64 + r0 + 8] = l1;
    }
}

// ---------------------------------------------------------------------------
// Kernel 3: merge up to 4 chunk partials per q-tile, normalize, write output.
// ---------------------------------------------------------------------------
__global__ __launch_bounds__(256) void merge_kernel(float* __restrict__ out) {
    const int qt = blockIdx.x;           // (b<<6)|qi
    const int b = qt >> 6, qi = qt & 63;
    const int nc = (qi >> 4) + 1;        // chunks of 16 k-tiles
    const int tid = threadIdx.x;
    const int r = tid >> 2, seg = (tid & 3) * 16;
    const float L2E = 1.4426950408889634f;

    float m = -1e30f;
    for (int c = 0; c < nc; c++)
        m = fmaxf(m, g_pm[(qt * 4 + c) * 64 + r]);
    float w[4];
    float lsum = 0.f;
    for (int c = 0; c < nc; c++) {
        w[c] = ex2f((g_pm[(qt * 4 + c) * 64 + r] - m) * L2E);
        lsum += g_pl[(qt * 4 + c) * 64 + r] * w[c];
    }
    float inv = 1.f / lsum;
    float4 acc[4];
#pragma unroll
    for (int gq = 0; gq < 4; gq++) acc[gq] = make_float4(0.f, 0.f, 0.f, 0.f);
    for (int c = 0; c < nc; c++) {
        const float4* oc = (const float4*)(g_po + (qt * 4 + c) * 4096 + r * 64 + seg);
        float wc = w[c];
#pragma unroll
        for (int gq = 0; gq < 4; gq++) {
            float4 v = oc[gq];
            acc[gq].x += v.x * wc; acc[gq].y += v.y * wc;
            acc[gq].z += v.z * wc; acc[gq].w += v.w * wc;
        }
    }
    float4* dst = (float4*)(out + ((size_t)b * TT + qi * 64 + r) * 64 + seg);
#pragma unroll
    for (int gq = 0; gq < 4; gq++) {
        float4 v;
        v.x = acc[gq].x * inv; v.y = acc[gq].y * inv;
        v.z = acc[gq].z * inv; v.w = acc[gq].w * inv;
        dst[gq] = v;
    }
}

// ---------------------------------------------------------------------------
extern "C" void kernel_launch(void* const* d_in, const int* in_sizes, int n_in,
                              void* d_out, int out_size) {
    const float* x  = (const float*)d_in[0];
    const float* Wq = (const float*)d_in[1];
    const float* Wk = (const float*)d_in[2];
    const float* Wv = (const float*)d_in[3];
    float* out = (float*)d_out;

    cudaFuncSetAttribute(proj_kernel, cudaFuncAttributeMaxDynamicSharedMemorySize, PRJ_SMEM);
    cudaFuncSetAttribute(attn_kernel, cudaFuncAttributeMaxDynamicSharedMemorySize, ATN_SMEM);

    prep_kernel<<<24, 256>>>(Wq, Wk, Wv);
    proj_kernel<<<dim3(128, 2), 256, PRJ_SMEM>>>(x);
    attn_kernel<<<1024, 128, ATN_SMEM>>>();
    merge_kernel<<<256, 256>>>(out);
}